// round 16
// baseline (speedup 1.0000x reference)
#include <cuda_runtime.h>
#include <cstddef>

#define BB 2048
#define TT 1024
#define DD 64
#define HH 32

typedef unsigned long long u64;

__device__ float g_gx0[(size_t)BB * TT * 96];
__device__ float g_gx1[(size_t)BB * TT * 96];
__device__ float g_h0[(size_t)BB * TT * 32];

__device__ __forceinline__ u64 ffma2(u64 a, u64 b, u64 c) {
    u64 d;
    asm("fma.rn.f32x2 %0, %1, %2, %3;" : "=l"(d) : "l"(a), "l"(b), "l"(c));
    return d;
}
__device__ __forceinline__ u64 pack2(float lo, float hi) {
    u64 r;
    asm("mov.b64 %0, {%1, %2};" : "=l"(r) : "f"(lo), "f"(hi));
    return r;
}
__device__ __forceinline__ float sum2(u64 v) {
    float a, b;
    asm("mov.b64 {%0, %1}, %2;" : "=f"(a), "=f"(b) : "l"(v));
    return a + b;
}
__device__ __forceinline__ float fast_sigmoid(float x) {
    float e;
    asm("ex2.approx.f32 %0, %1;" : "=f"(e) : "f"(-1.4426950408889634f * x));
    float r;
    asm("rcp.approx.f32 %0, %1;" : "=f"(r) : "f"(1.0f + e));
    return r;
}
__device__ __forceinline__ float fast_tanh(float x) {
    return fmaf(2.0f, fast_sigmoid(2.0f * x), -1.0f);
}

// ================= Phase A: gx0 = x @ W_ih0^T + b_ih0 (K=64), 16 tokens/warp =================
// Weight-LDS amortized over 16 tokens: crossbar/token 64 -> 40 cyc (was the binding pipe).
__global__ void __launch_bounds__(256, 1)
gx0_kernel(const float* __restrict__ x,
           const float* __restrict__ wih0, const float* __restrict__ bih0)
{
    extern __shared__ float4 sm4[];
    float4* w4 = sm4;                 // [16 kk][96 gate], 24KB
    float4* xs = sm4 + 1536;          // [8 warp][16 tok][16 f4], 32KB

    const int tid = threadIdx.x, warp = tid >> 5, lane = tid & 31;
    for (int i = tid; i < 1536; i += 256) {
        int g = i % 96, kk = i / 96;
        w4[kk * 96 + g] = *(const float4*)(wih0 + g * 64 + kk * 4);
    }
    __syncthreads();
    const float b0 = bih0[lane], b1 = bih0[32 + lane], b2 = bih0[64 + lane];

    const int row = blockIdx.x;
    // warp covers tokens it*128 + warp*16 .. +15 ; its x f4-range starts at that*16
    const float4* xg = (const float4*)(x + (size_t)row * TT * DD) + warp * 256;
    float* gw = g_gx0 + ((size_t)row * TT + warp * 16) * 96;
    float4* xsw = xs + warp * 256;

    float4 xb[8];
#pragma unroll
    for (int i = 0; i < 8; i++) xb[i] = xg[i * 32 + lane];
    xg += 2048;                        // 128 tokens * 16 f4

    for (int it = 0; it < 8; it++) {
#pragma unroll
        for (int i = 0; i < 8; i++) xsw[i * 32 + lane] = xb[i];
        __syncwarp();
        if (it + 1 < 8) {
#pragma unroll
            for (int i = 0; i < 8; i++) xb[i] = xg[i * 32 + lane];
            xg += 2048;
        }
        u64 a0[16], a1[16], a2[16];
#pragma unroll
        for (int t = 0; t < 16; t++) {
            a0[t] = pack2(b0, 0.f); a1[t] = pack2(b1, 0.f); a2[t] = pack2(b2, 0.f);
        }
#pragma unroll 2
        for (int kk = 0; kk < 16; kk++) {
            ulonglong2 wr = *(const ulonglong2*)(w4 + kk * 96 + lane);
            ulonglong2 wz = *(const ulonglong2*)(w4 + kk * 96 + 32 + lane);
            ulonglong2 wn = *(const ulonglong2*)(w4 + kk * 96 + 64 + lane);
#pragma unroll
            for (int t = 0; t < 16; t++) {
                ulonglong2 xv = *(const ulonglong2*)(xsw + t * 16 + kk);
                a0[t] = ffma2(wr.x, xv.x, a0[t]); a0[t] = ffma2(wr.y, xv.y, a0[t]);
                a1[t] = ffma2(wz.x, xv.x, a1[t]); a1[t] = ffma2(wz.y, xv.y, a1[t]);
                a2[t] = ffma2(wn.x, xv.x, a2[t]); a2[t] = ffma2(wn.y, xv.y, a2[t]);
            }
        }
#pragma unroll
        for (int t = 0; t < 16; t++) {
            float* o = gw + (it * 128 + t) * 96;
            o[lane] = sum2(a0[t]); o[32 + lane] = sum2(a1[t]); o[64 + lane] = sum2(a2[t]);
        }
        __syncwarp();
    }
}

// ================= Phase C: gxl1 = h0_all @ W_ih1^T + b_ih1 (K=32), 16 tokens/warp =================
__global__ void __launch_bounds__(256, 1)
gxl1_kernel(const float* __restrict__ wih1, const float* __restrict__ bih1)
{
    __shared__ float4 w4[8 * 96];      // 12KB
    __shared__ float4 hsh[8 * 128];    // [8 warp][16 tok][8 f4], 16KB

    const int tid = threadIdx.x, warp = tid >> 5, lane = tid & 31;
    for (int i = tid; i < 768; i += 256) {
        int g = i % 96, kk = i / 96;
        w4[kk * 96 + g] = *(const float4*)(wih1 + g * 32 + kk * 4);
    }
    __syncthreads();
    const float b0 = bih1[lane], b1 = bih1[32 + lane], b2 = bih1[64 + lane];

    const int row = blockIdx.x;
    const float4* hg = (const float4*)(g_h0 + (size_t)row * TT * 32) + warp * 128;
    float* gw = g_gx1 + ((size_t)row * TT + warp * 16) * 96;
    float4* hsw = hsh + warp * 128;

    float4 hb[4];
#pragma unroll
    for (int i = 0; i < 4; i++) hb[i] = hg[i * 32 + lane];
    hg += 1024;                        // 128 tokens * 8 f4

    for (int it = 0; it < 8; it++) {
#pragma unroll
        for (int i = 0; i < 4; i++) hsw[i * 32 + lane] = hb[i];
        __syncwarp();
        if (it + 1 < 8) {
#pragma unroll
            for (int i = 0; i < 4; i++) hb[i] = hg[i * 32 + lane];
            hg += 1024;
        }
        u64 a0[16], a1[16], a2[16];
#pragma unroll
        for (int t = 0; t < 16; t++) {
            a0[t] = pack2(b0, 0.f); a1[t] = pack2(b1, 0.f); a2[t] = pack2(b2, 0.f);
        }
#pragma unroll 2
        for (int kk = 0; kk < 8; kk++) {
            ulonglong2 wr = *(const ulonglong2*)(w4 + kk * 96 + lane);
            ulonglong2 wz = *(const ulonglong2*)(w4 + kk * 96 + 32 + lane);
            ulonglong2 wn = *(const ulonglong2*)(w4 + kk * 96 + 64 + lane);
#pragma unroll
            for (int t = 0; t < 16; t++) {
                ulonglong2 hv = *(const ulonglong2*)(hsw + t * 8 + kk);
                a0[t] = ffma2(wr.x, hv.x, a0[t]); a0[t] = ffma2(wr.y, hv.y, a0[t]);
                a1[t] = ffma2(wz.x, hv.x, a1[t]); a1[t] = ffma2(wz.y, hv.y, a1[t]);
                a2[t] = ffma2(wn.x, hv.x, a2[t]); a2[t] = ffma2(wn.y, hv.y, a2[t]);
            }
        }
#pragma unroll
        for (int t = 0; t < 16; t++) {
            float* o = gw + (it * 128 + t) * 96;
            o[lane] = sum2(a0[t]); o[32 + lane] = sum2(a1[t]); o[64 + lane] = sum2(a2[t]);
        }
        __syncwarp();
    }
}

// recurrence step (R14-proven): 2 rows, register weights, split accumulator chains.
__device__ __forceinline__ void rec_step(const float* __restrict__ hw,
                                         const u64* __restrict__ wr,
                                         const u64* __restrict__ wz,
                                         const u64* __restrict__ wn,
                                         float xra, float xza, float xna,
                                         float xrb, float xzb, float xnb,
                                         float BN, float& HA, float& HB)
{
    u64 grA = pack2(xra, 0.f), gzA = pack2(xza, 0.f), gnA = pack2(BN, 0.f);
    u64 grB = pack2(xrb, 0.f), gzB = pack2(xzb, 0.f), gnB = pack2(BN, 0.f);
    u64 hrA = pack2(0.f, 0.f), hzA = pack2(0.f, 0.f), hnA = pack2(0.f, 0.f);
    u64 hrB = pack2(0.f, 0.f), hzB = pack2(0.f, 0.f), hnB = pack2(0.f, 0.f);
#pragma unroll
    for (int kk = 0; kk < 4; kk++) {
        ulonglong2 va = *(const ulonglong2*)(hw + kk * 4);
        ulonglong2 vb = *(const ulonglong2*)(hw + 32 + kk * 4);
        grA = ffma2(wr[2*kk], va.x, grA); grA = ffma2(wr[2*kk+1], va.y, grA);
        gzA = ffma2(wz[2*kk], va.x, gzA); gzA = ffma2(wz[2*kk+1], va.y, gzA);
        gnA = ffma2(wn[2*kk], va.x, gnA); gnA = ffma2(wn[2*kk+1], va.y, gnA);
        grB = ffma2(wr[2*kk], vb.x, grB); grB = ffma2(wr[2*kk+1], vb.y, grB);
        gzB = ffma2(wz[2*kk], vb.x, gzB); gzB = ffma2(wz[2*kk+1], vb.y, gzB);
        gnB = ffma2(wn[2*kk], vb.x, gnB); gnB = ffma2(wn[2*kk+1], vb.y, gnB);
    }
#pragma unroll
    for (int kk = 4; kk < 8; kk++) {
        ulonglong2 va = *(const ulonglong2*)(hw + kk * 4);
        ulonglong2 vb = *(const ulonglong2*)(hw + 32 + kk * 4);
        hrA = ffma2(wr[2*kk], va.x, hrA); hrA = ffma2(wr[2*kk+1], va.y, hrA);
        hzA = ffma2(wz[2*kk], va.x, hzA); hzA = ffma2(wz[2*kk+1], va.y, hzA);
        hnA = ffma2(wn[2*kk], va.x, hnA); hnA = ffma2(wn[2*kk+1], va.y, hnA);
        hrB = ffma2(wr[2*kk], vb.x, hrB); hrB = ffma2(wr[2*kk+1], vb.y, hrB);
        hzB = ffma2(wz[2*kk], vb.x, hzB); hzB = ffma2(wz[2*kk+1], vb.y, hzB);
        hnB = ffma2(wn[2*kk], vb.x, hnB); hnB = ffma2(wn[2*kk+1], vb.y, hnB);
    }
    float rA = fast_sigmoid(sum2(grA) + sum2(hrA));
    float zA = fast_sigmoid(sum2(gzA) + sum2(hzA));
    float nA = fast_tanh(xna + rA * (sum2(gnA) + sum2(hnA)));
    HA = nA + zA * (HA - nA);
    float rB = fast_sigmoid(sum2(grB) + sum2(hrB));
    float zB = fast_sigmoid(sum2(gzB) + sum2(hzB));
    float nB = fast_tanh(xnb + rB * (sum2(gnB) + sum2(hnB)));
    HB = nB + zB * (HB - nB);
}

// ================= Phase B: layer-0 recurrence (R14-proven) =================
__global__ void __launch_bounds__(256, 1)
rec0_kernel(const float* __restrict__ whh0, const float* __restrict__ bhh0,
            float* __restrict__ out)
{
    __shared__ float hs[512];
    const int tid = threadIdx.x, warp = tid >> 5, lane = tid & 31;
    const int r0 = blockIdx.x * 16 + warp * 2;

    u64 wr[16], wz[16], wn[16];
#pragma unroll
    for (int i = 0; i < 8; i++) {
        ulonglong2 a = *(const ulonglong2*)(whh0 + lane * 32 + i * 4);
        ulonglong2 b = *(const ulonglong2*)(whh0 + (32 + lane) * 32 + i * 4);
        ulonglong2 c = *(const ulonglong2*)(whh0 + (64 + lane) * 32 + i * 4);
        wr[2 * i] = a.x; wr[2 * i + 1] = a.y;
        wz[2 * i] = b.x; wz[2 * i + 1] = b.y;
        wn[2 * i] = c.x; wn[2 * i + 1] = c.y;
    }
    const float bR = bhh0[lane], bZ = bhh0[32 + lane], bN = bhh0[64 + lane];

    float* hw = hs + warp * 64;
    hw[lane] = 0.f; hw[32 + lane] = 0.f;
    float ha = 0.f, hb = 0.f;

    const float* ga = g_gx0 + (size_t)r0 * TT * 96;
    const float* gb = ga + (size_t)TT * 96;
    float* hoA = g_h0 + (size_t)r0 * TT * 32;
    float* hoB = hoA + (size_t)TT * 32;

    float fa[4][3], fb[4][3];
#pragma unroll
    for (int s = 0; s < 4; s++) {
        fa[s][0] = ga[lane]; fa[s][1] = ga[32 + lane]; fa[s][2] = ga[64 + lane]; ga += 96;
        fb[s][0] = gb[lane]; fb[s][1] = gb[32 + lane]; fb[s][2] = gb[64 + lane]; gb += 96;
    }
    __syncwarp();

#pragma unroll 4
    for (int t = 0; t < TT; t++) {
        const int s = t & 3;
        float xra = fa[s][0] + bR, xza = fa[s][1] + bZ, xna = fa[s][2];
        float xrb = fb[s][0] + bR, xzb = fb[s][1] + bZ, xnb = fb[s][2];
        if (t + 4 < TT) {
            fa[s][0] = ga[lane]; fa[s][1] = ga[32 + lane]; fa[s][2] = ga[64 + lane]; ga += 96;
            fb[s][0] = gb[lane]; fb[s][1] = gb[32 + lane]; fb[s][2] = gb[64 + lane]; gb += 96;
        }
        rec_step(hw, wr, wz, wn, xra, xza, xna, xrb, xzb, xnb, bN, ha, hb);
        hoA[t * 32 + lane] = ha;
        hoB[t * 32 + lane] = hb;
        __syncwarp();
        hw[lane] = ha; hw[32 + lane] = hb;
        __syncwarp();
    }
    out[BB + r0 * HH + lane]       = ha;
    out[BB + (r0 + 1) * HH + lane] = hb;
}

// ================= Phase D: layer-1 recurrence + classifier (R14-proven) =================
__global__ void __launch_bounds__(256, 1)
rec1_kernel(const float* __restrict__ whh1, const float* __restrict__ bhh1,
            const float* __restrict__ wcls, const float* __restrict__ bcls,
            float* __restrict__ out)
{
    __shared__ float hs[512];
    const int tid = threadIdx.x, warp = tid >> 5, lane = tid & 31;
    const int r0 = blockIdx.x * 16 + warp * 2;

    u64 wr[16], wz[16], wn[16];
#pragma unroll
    for (int i = 0; i < 8; i++) {
        ulonglong2 a = *(const ulonglong2*)(whh1 + lane * 32 + i * 4);
        ulonglong2 b = *(const ulonglong2*)(whh1 + (32 + lane) * 32 + i * 4);
        ulonglong2 c = *(const ulonglong2*)(whh1 + (64 + lane) * 32 + i * 4);
        wr[2 * i] = a.x; wr[2 * i + 1] = a.y;
        wz[2 * i] = b.x; wz[2 * i + 1] = b.y;
        wn[2 * i] = c.x; wn[2 * i + 1] = c.y;
    }
    const float bR = bhh1[lane], bZ = bhh1[32 + lane], bN = bhh1[64 + lane];

    float* hw = hs + warp * 64;
    hw[lane] = 0.f; hw[32 + lane] = 0.f;
    float ha = 0.f, hb = 0.f;

    const float* ga = g_gx1 + (size_t)r0 * TT * 96;
    const float* gb = ga + (size_t)TT * 96;

    float fa[4][3], fb[4][3];
#pragma unroll
    for (int s = 0; s < 4; s++) {
        fa[s][0] = ga[lane]; fa[s][1] = ga[32 + lane]; fa[s][2] = ga[64 + lane]; ga += 96;
        fb[s][0] = gb[lane]; fb[s][1] = gb[32 + lane]; fb[s][2] = gb[64 + lane]; gb += 96;
    }
    __syncwarp();

#pragma unroll 4
    for (int t = 0; t < TT; t++) {
        const int s = t & 3;
        float xra = fa[s][0] + bR, xza = fa[s][1] + bZ, xna = fa[s][2];
        float xrb = fb[s][0] + bR, xzb = fb[s][1] + bZ, xnb = fb[s][2];
        if (t + 4 < TT) {
            fa[s][0] = ga[lane]; fa[s][1] = ga[32 + lane]; fa[s][2] = ga[64 + lane]; ga += 96;
            fb[s][0] = gb[lane]; fb[s][1] = gb[32 + lane]; fb[s][2] = gb[64 + lane]; gb += 96;
        }
        rec_step(hw, wr, wz, wn, xra, xza, xna, xrb, xzb, xnb, bN, ha, hb);
        __syncwarp();
        hw[lane] = ha; hw[32 + lane] = hb;
        __syncwarp();
    }

    out[BB + BB * HH + r0 * HH + lane]       = ha;
    out[BB + BB * HH + (r0 + 1) * HH + lane] = hb;
    const float wc = wcls[lane];
    float pA = ha * wc, pB = hb * wc;
#pragma unroll
    for (int off = 16; off; off >>= 1) {
        pA += __shfl_xor_sync(0xffffffffu, pA, off);
        pB += __shfl_xor_sync(0xffffffffu, pB, off);
    }
    if (lane == 0) {
        float bc = bcls[0];
        out[r0]     = fast_sigmoid(pA + bc);
        out[r0 + 1] = fast_sigmoid(pB + bc);
    }
}

extern "C" void kernel_launch(void* const* d_in, const int* in_sizes, int n_in,
                              void* d_out, int out_size) {
    (void)in_sizes; (void)n_in; (void)out_size;
    const float* x    = (const float*)d_in[0];
    const float* wih0 = (const float*)d_in[1];
    const float* whh0 = (const float*)d_in[2];
    const float* bih0 = (const float*)d_in[3];
    const float* bhh0 = (const float*)d_in[4];
    const float* wih1 = (const float*)d_in[5];
    const float* whh1 = (const float*)d_in[6];
    const float* bih1 = (const float*)d_in[7];
    const float* bhh1 = (const float*)d_in[8];
    const float* wcls = (const float*)d_in[9];
    const float* bcls = (const float*)d_in[10];
    float* out = (float*)d_out;

    const int gx0_smem = (1536 + 2048) * 16;   // 56KB dynamic
    cudaFuncSetAttribute(gx0_kernel, cudaFuncAttributeMaxDynamicSharedMemorySize, gx0_smem);
    gx0_kernel<<<BB, 256, gx0_smem>>>(x, wih0, bih0);
    rec0_kernel<<<128, 256>>>(whh0, bhh0, out);
    gxl1_kernel<<<BB, 256>>>(wih1, bih1);
    rec1_kernel<<<128, 256>>>(whh1, bhh1, wcls, bcls, out);
}

// round 17
// speedup vs baseline: 1.4968x; 1.4968x over previous
#include <cuda_runtime.h>
#include <cstddef>

#define BB 2048
#define TT 1024
#define DD 64
#define HH 32
#define CHK 8          // time chunks
#define CT  128        // steps per chunk

typedef unsigned long long u64;

__device__ float g_gx0[(size_t)BB * TT * 96];
__device__ float g_gx1[(size_t)BB * TT * 96];
__device__ float g_h0[(size_t)BB * TT * 32];
__device__ float g_hst0[BB * 32];    // rec0 h-state between chunks
__device__ float g_hst1[BB * 32];    // rec1 h-state between chunks

__device__ __forceinline__ u64 ffma2(u64 a, u64 b, u64 c) {
    u64 d;
    asm("fma.rn.f32x2 %0, %1, %2, %3;" : "=l"(d) : "l"(a), "l"(b), "l"(c));
    return d;
}
__device__ __forceinline__ u64 pack2(float lo, float hi) {
    u64 r;
    asm("mov.b64 %0, {%1, %2};" : "=l"(r) : "f"(lo), "f"(hi));
    return r;
}
__device__ __forceinline__ float sum2(u64 v) {
    float a, b;
    asm("mov.b64 {%0, %1}, %2;" : "=f"(a), "=f"(b) : "l"(v));
    return a + b;
}
__device__ __forceinline__ float fast_sigmoid(float x) {
    float e;
    asm("ex2.approx.f32 %0, %1;" : "=f"(e) : "f"(-1.4426950408889634f * x));
    float r;
    asm("rcp.approx.f32 %0, %1;" : "=f"(r) : "f"(1.0f + e));
    return r;
}
__device__ __forceinline__ float fast_tanh(float x) {
    return fmaf(2.0f, fast_sigmoid(2.0f * x), -1.0f);
}

// ============ gx0 chunk: gx0[:, c*CT:(c+1)*CT] = x·W_ih0^T + b (K=64) ============
// grid 2048 (one row/block); 8 warps x 16 tokens (2 iters of the R12-proven 8-token body).
__global__ void __launch_bounds__(256, 1)
gx0_kernel(const float* __restrict__ x,
           const float* __restrict__ wih0, const float* __restrict__ bih0, int c)
{
    __shared__ float4 w4[16 * 96];
    __shared__ float4 xs[8 * 128];

    const int tid = threadIdx.x, warp = tid >> 5, lane = tid & 31;
    for (int i = tid; i < 1536; i += 256) {
        int g = i % 96, kk = i / 96;
        w4[kk * 96 + g] = *(const float4*)(wih0 + g * 64 + kk * 4);
    }
    __syncthreads();
    const float b0 = bih0[lane], b1 = bih0[32 + lane], b2 = bih0[64 + lane];

    const int row = blockIdx.x;
    const int tokbase = c * CT + warp * 16;
    const float4* xg = (const float4*)x + ((size_t)row * TT + tokbase) * 16;
    float* gw = g_gx0 + ((size_t)row * TT + tokbase) * 96;
    float4* xsw = xs + warp * 128;

    for (int it = 0; it < 2; it++) {
#pragma unroll
        for (int i = 0; i < 4; i++) xsw[i * 32 + lane] = xg[it * 128 + i * 32 + lane];
        __syncwarp();
        u64 a0[8], a1[8], a2[8];
#pragma unroll
        for (int t = 0; t < 8; t++) {
            a0[t] = pack2(b0, 0.f); a1[t] = pack2(b1, 0.f); a2[t] = pack2(b2, 0.f);
        }
#pragma unroll 4
        for (int kk = 0; kk < 16; kk++) {
            ulonglong2 wr = *(const ulonglong2*)(w4 + kk * 96 + lane);
            ulonglong2 wz = *(const ulonglong2*)(w4 + kk * 96 + 32 + lane);
            ulonglong2 wn = *(const ulonglong2*)(w4 + kk * 96 + 64 + lane);
#pragma unroll
            for (int t = 0; t < 8; t++) {
                ulonglong2 xv = *(const ulonglong2*)(xsw + t * 16 + kk);
                a0[t] = ffma2(wr.x, xv.x, a0[t]); a0[t] = ffma2(wr.y, xv.y, a0[t]);
                a1[t] = ffma2(wz.x, xv.x, a1[t]); a1[t] = ffma2(wz.y, xv.y, a1[t]);
                a2[t] = ffma2(wn.x, xv.x, a2[t]); a2[t] = ffma2(wn.y, xv.y, a2[t]);
            }
        }
#pragma unroll
        for (int t = 0; t < 8; t++) {
            float* o = gw + (it * 8 + t) * 96;
            o[lane] = sum2(a0[t]); o[32 + lane] = sum2(a1[t]); o[64 + lane] = sum2(a2[t]);
        }
        __syncwarp();
    }
}

// ============ gxl1 chunk: gx1[:, chunk] = h0·W_ih1^T + b (K=32) ============
__global__ void __launch_bounds__(256, 1)
gxl1_kernel(const float* __restrict__ wih1, const float* __restrict__ bih1, int c)
{
    __shared__ float4 w4[8 * 96];
    __shared__ float4 hsh[8 * 64];

    const int tid = threadIdx.x, warp = tid >> 5, lane = tid & 31;
    for (int i = tid; i < 768; i += 256) {
        int g = i % 96, kk = i / 96;
        w4[kk * 96 + g] = *(const float4*)(wih1 + g * 32 + kk * 4);
    }
    __syncthreads();
    const float b0 = bih1[lane], b1 = bih1[32 + lane], b2 = bih1[64 + lane];

    const int row = blockIdx.x;
    const int tokbase = c * CT + warp * 16;
    const float4* hg = (const float4*)g_h0 + ((size_t)row * TT + tokbase) * 8;
    float* gw = g_gx1 + ((size_t)row * TT + tokbase) * 96;
    float4* hsw = hsh + warp * 64;

    for (int it = 0; it < 2; it++) {
#pragma unroll
        for (int i = 0; i < 2; i++) hsw[i * 32 + lane] = hg[it * 64 + i * 32 + lane];
        __syncwarp();
        u64 a0[8], a1[8], a2[8];
#pragma unroll
        for (int t = 0; t < 8; t++) {
            a0[t] = pack2(b0, 0.f); a1[t] = pack2(b1, 0.f); a2[t] = pack2(b2, 0.f);
        }
#pragma unroll 4
        for (int kk = 0; kk < 8; kk++) {
            ulonglong2 wr = *(const ulonglong2*)(w4 + kk * 96 + lane);
            ulonglong2 wz = *(const ulonglong2*)(w4 + kk * 96 + 32 + lane);
            ulonglong2 wn = *(const ulonglong2*)(w4 + kk * 96 + 64 + lane);
#pragma unroll
            for (int t = 0; t < 8; t++) {
                ulonglong2 hv = *(const ulonglong2*)(hsw + t * 8 + kk);
                a0[t] = ffma2(wr.x, hv.x, a0[t]); a0[t] = ffma2(wr.y, hv.y, a0[t]);
                a1[t] = ffma2(wz.x, hv.x, a1[t]); a1[t] = ffma2(wz.y, hv.y, a1[t]);
                a2[t] = ffma2(wn.x, hv.x, a2[t]); a2[t] = ffma2(wn.y, hv.y, a2[t]);
            }
        }
#pragma unroll
        for (int t = 0; t < 8; t++) {
            float* o = gw + (it * 8 + t) * 96;
            o[lane] = sum2(a0[t]); o[32 + lane] = sum2(a1[t]); o[64 + lane] = sum2(a2[t]);
        }
        __syncwarp();
    }
}

// recurrence step (R14-proven): 2 rows, register weights, split accumulator chains
__device__ __forceinline__ void rec_step(const float* __restrict__ hw,
                                         const u64* __restrict__ wr,
                                         const u64* __restrict__ wz,
                                         const u64* __restrict__ wn,
                                         float xra, float xza, float xna,
                                         float xrb, float xzb, float xnb,
                                         float BN, float& HA, float& HB)
{
    u64 grA = pack2(xra, 0.f), gzA = pack2(xza, 0.f), gnA = pack2(BN, 0.f);
    u64 grB = pack2(xrb, 0.f), gzB = pack2(xzb, 0.f), gnB = pack2(BN, 0.f);
    u64 hrA = pack2(0.f, 0.f), hzA = pack2(0.f, 0.f), hnA = pack2(0.f, 0.f);
    u64 hrB = pack2(0.f, 0.f), hzB = pack2(0.f, 0.f), hnB = pack2(0.f, 0.f);
#pragma unroll
    for (int kk = 0; kk < 4; kk++) {
        ulonglong2 va = *(const ulonglong2*)(hw + kk * 4);
        ulonglong2 vb = *(const ulonglong2*)(hw + 32 + kk * 4);
        grA = ffma2(wr[2*kk], va.x, grA); grA = ffma2(wr[2*kk+1], va.y, grA);
        gzA = ffma2(wz[2*kk], va.x, gzA); gzA = ffma2(wz[2*kk+1], va.y, gzA);
        gnA = ffma2(wn[2*kk], va.x, gnA); gnA = ffma2(wn[2*kk+1], va.y, gnA);
        grB = ffma2(wr[2*kk], vb.x, grB); grB = ffma2(wr[2*kk+1], vb.y, grB);
        gzB = ffma2(wz[2*kk], vb.x, gzB); gzB = ffma2(wz[2*kk+1], vb.y, gzB);
        gnB = ffma2(wn[2*kk], vb.x, gnB); gnB = ffma2(wn[2*kk+1], vb.y, gnB);
    }
#pragma unroll
    for (int kk = 4; kk < 8; kk++) {
        ulonglong2 va = *(const ulonglong2*)(hw + kk * 4);
        ulonglong2 vb = *(const ulonglong2*)(hw + 32 + kk * 4);
        hrA = ffma2(wr[2*kk], va.x, hrA); hrA = ffma2(wr[2*kk+1], va.y, hrA);
        hzA = ffma2(wz[2*kk], va.x, hzA); hzA = ffma2(wz[2*kk+1], va.y, hzA);
        hnA = ffma2(wn[2*kk], va.x, hnA); hnA = ffma2(wn[2*kk+1], va.y, hnA);
        hrB = ffma2(wr[2*kk], vb.x, hrB); hrB = ffma2(wr[2*kk+1], vb.y, hrB);
        hzB = ffma2(wz[2*kk], vb.x, hzB); hzB = ffma2(wz[2*kk+1], vb.y, hzB);
        hnB = ffma2(wn[2*kk], vb.x, hnB); hnB = ffma2(wn[2*kk+1], vb.y, hnB);
    }
    float rA = fast_sigmoid(sum2(grA) + sum2(hrA));
    float zA = fast_sigmoid(sum2(gzA) + sum2(hzA));
    float nA = fast_tanh(xna + rA * (sum2(gnA) + sum2(hnA)));
    HA = nA + zA * (HA - nA);
    float rB = fast_sigmoid(sum2(grB) + sum2(hrB));
    float zB = fast_sigmoid(sum2(gzB) + sum2(hzB));
    float nB = fast_tanh(xnb + rB * (sum2(gnB) + sum2(hnB)));
    HB = nB + zB * (HB - nB);
}

// ============ rec0 chunk: layer-0 recurrence over steps [c*CT, (c+1)*CT) ============
__global__ void __launch_bounds__(256, 1)
rec0_kernel(const float* __restrict__ whh0, const float* __restrict__ bhh0,
            float* __restrict__ out, int c)
{
    __shared__ float hs[512];
    const int tid = threadIdx.x, warp = tid >> 5, lane = tid & 31;
    const int r0 = blockIdx.x * 16 + warp * 2;

    u64 wr[16], wz[16], wn[16];
#pragma unroll
    for (int i = 0; i < 8; i++) {
        ulonglong2 a = *(const ulonglong2*)(whh0 + lane * 32 + i * 4);
        ulonglong2 b = *(const ulonglong2*)(whh0 + (32 + lane) * 32 + i * 4);
        ulonglong2 cc = *(const ulonglong2*)(whh0 + (64 + lane) * 32 + i * 4);
        wr[2 * i] = a.x; wr[2 * i + 1] = a.y;
        wz[2 * i] = b.x; wz[2 * i + 1] = b.y;
        wn[2 * i] = cc.x; wn[2 * i + 1] = cc.y;
    }
    const float bR = bhh0[lane], bZ = bhh0[32 + lane], bN = bhh0[64 + lane];

    float ha, hb;
    if (c == 0) { ha = 0.f; hb = 0.f; }
    else { ha = g_hst0[r0 * 32 + lane]; hb = g_hst0[(r0 + 1) * 32 + lane]; }
    float* hw = hs + warp * 64;
    hw[lane] = ha; hw[32 + lane] = hb;

    const float* ga = g_gx0 + ((size_t)r0 * TT + c * CT) * 96;
    const float* gb = ga + (size_t)TT * 96;
    float* hoA = g_h0 + ((size_t)r0 * TT + c * CT) * 32;
    float* hoB = hoA + (size_t)TT * 32;

    float fa[4][3], fb[4][3];
#pragma unroll
    for (int s = 0; s < 4; s++) {
        fa[s][0] = ga[lane]; fa[s][1] = ga[32 + lane]; fa[s][2] = ga[64 + lane]; ga += 96;
        fb[s][0] = gb[lane]; fb[s][1] = gb[32 + lane]; fb[s][2] = gb[64 + lane]; gb += 96;
    }
    __syncwarp();

#pragma unroll 4
    for (int t = 0; t < CT; t++) {
        const int s = t & 3;
        float xra = fa[s][0] + bR, xza = fa[s][1] + bZ, xna = fa[s][2];
        float xrb = fb[s][0] + bR, xzb = fb[s][1] + bZ, xnb = fb[s][2];
        if (t + 4 < CT) {
            fa[s][0] = ga[lane]; fa[s][1] = ga[32 + lane]; fa[s][2] = ga[64 + lane]; ga += 96;
            fb[s][0] = gb[lane]; fb[s][1] = gb[32 + lane]; fb[s][2] = gb[64 + lane]; gb += 96;
        }
        rec_step(hw, wr, wz, wn, xra, xza, xna, xrb, xzb, xnb, bN, ha, hb);
        hoA[t * 32 + lane] = ha;
        hoB[t * 32 + lane] = hb;
        __syncwarp();
        hw[lane] = ha; hw[32 + lane] = hb;
        __syncwarp();
    }
    g_hst0[r0 * 32 + lane]       = ha;
    g_hst0[(r0 + 1) * 32 + lane] = hb;
    if (c == CHK - 1) {
        out[BB + r0 * HH + lane]       = ha;
        out[BB + (r0 + 1) * HH + lane] = hb;
    }
}

// ============ rec1 chunk: layer-1 recurrence; last chunk writes h_last1 + y ============
__global__ void __launch_bounds__(256, 1)
rec1_kernel(const float* __restrict__ whh1, const float* __restrict__ bhh1,
            const float* __restrict__ wcls, const float* __restrict__ bcls,
            float* __restrict__ out, int c)
{
    __shared__ float hs[512];
    const int tid = threadIdx.x, warp = tid >> 5, lane = tid & 31;
    const int r0 = blockIdx.x * 16 + warp * 2;

    u64 wr[16], wz[16], wn[16];
#pragma unroll
    for (int i = 0; i < 8; i++) {
        ulonglong2 a = *(const ulonglong2*)(whh1 + lane * 32 + i * 4);
        ulonglong2 b = *(const ulonglong2*)(whh1 + (32 + lane) * 32 + i * 4);
        ulonglong2 cc = *(const ulonglong2*)(whh1 + (64 + lane) * 32 + i * 4);
        wr[2 * i] = a.x; wr[2 * i + 1] = a.y;
        wz[2 * i] = b.x; wz[2 * i + 1] = b.y;
        wn[2 * i] = cc.x; wn[2 * i + 1] = cc.y;
    }
    const float bR = bhh1[lane], bZ = bhh1[32 + lane], bN = bhh1[64 + lane];

    float ha, hb;
    if (c == 0) { ha = 0.f; hb = 0.f; }
    else { ha = g_hst1[r0 * 32 + lane]; hb = g_hst1[(r0 + 1) * 32 + lane]; }
    float* hw = hs + warp * 64;
    hw[lane] = ha; hw[32 + lane] = hb;

    const float* ga = g_gx1 + ((size_t)r0 * TT + c * CT) * 96;
    const float* gb = ga + (size_t)TT * 96;

    float fa[4][3], fb[4][3];
#pragma unroll
    for (int s = 0; s < 4; s++) {
        fa[s][0] = ga[lane]; fa[s][1] = ga[32 + lane]; fa[s][2] = ga[64 + lane]; ga += 96;
        fb[s][0] = gb[lane]; fb[s][1] = gb[32 + lane]; fb[s][2] = gb[64 + lane]; gb += 96;
    }
    __syncwarp();

#pragma unroll 4
    for (int t = 0; t < CT; t++) {
        const int s = t & 3;
        float xra = fa[s][0] + bR, xza = fa[s][1] + bZ, xna = fa[s][2];
        float xrb = fb[s][0] + bR, xzb = fb[s][1] + bZ, xnb = fb[s][2];
        if (t + 4 < CT) {
            fa[s][0] = ga[lane]; fa[s][1] = ga[32 + lane]; fa[s][2] = ga[64 + lane]; ga += 96;
            fb[s][0] = gb[lane]; fb[s][1] = gb[32 + lane]; fb[s][2] = gb[64 + lane]; gb += 96;
        }
        rec_step(hw, wr, wz, wn, xra, xza, xna, xrb, xzb, xnb, bN, ha, hb);
        __syncwarp();
        hw[lane] = ha; hw[32 + lane] = hb;
        __syncwarp();
    }

    g_hst1[r0 * 32 + lane]       = ha;
    g_hst1[(r0 + 1) * 32 + lane] = hb;
    if (c == CHK - 1) {
        out[BB + BB * HH + r0 * HH + lane]       = ha;
        out[BB + BB * HH + (r0 + 1) * HH + lane] = hb;
        const float wc = wcls[lane];
        float pA = ha * wc, pB = hb * wc;
#pragma unroll
        for (int off = 16; off; off >>= 1) {
            pA += __shfl_xor_sync(0xffffffffu, pA, off);
            pB += __shfl_xor_sync(0xffffffffu, pB, off);
        }
        if (lane == 0) {
            float bc = bcls[0];
            out[r0]     = fast_sigmoid(pA + bc);
            out[r0 + 1] = fast_sigmoid(pB + bc);
        }
    }
}

// ---- stream/event infrastructure: created lazily on the (uncaptured) correctness call ----
static cudaStream_t s_gx, s_r0, s_r1;
static cudaEvent_t evFork, evG[CHK], evR0[CHK], evJoin;
static bool g_init = false;

extern "C" void kernel_launch(void* const* d_in, const int* in_sizes, int n_in,
                              void* d_out, int out_size) {
    (void)in_sizes; (void)n_in; (void)out_size;
    const float* x    = (const float*)d_in[0];
    const float* wih0 = (const float*)d_in[1];
    const float* whh0 = (const float*)d_in[2];
    const float* bih0 = (const float*)d_in[3];
    const float* bhh0 = (const float*)d_in[4];
    const float* wih1 = (const float*)d_in[5];
    const float* whh1 = (const float*)d_in[6];
    const float* bih1 = (const float*)d_in[7];
    const float* bhh1 = (const float*)d_in[8];
    const float* wcls = (const float*)d_in[9];
    const float* bcls = (const float*)d_in[10];
    float* out = (float*)d_out;

    if (!g_init) {
        cudaStreamCreateWithFlags(&s_gx, cudaStreamNonBlocking);
        cudaStreamCreateWithFlags(&s_r0, cudaStreamNonBlocking);
        cudaStreamCreateWithFlags(&s_r1, cudaStreamNonBlocking);
        cudaEventCreateWithFlags(&evFork, cudaEventDisableTiming);
        cudaEventCreateWithFlags(&evJoin, cudaEventDisableTiming);
        for (int k = 0; k < CHK; k++) {
            cudaEventCreateWithFlags(&evG[k],  cudaEventDisableTiming);
            cudaEventCreateWithFlags(&evR0[k], cudaEventDisableTiming);
        }
        g_init = true;
    }

    // fork from the (possibly capturing) default stream
    cudaEventRecord(evFork, 0);
    cudaStreamWaitEvent(s_gx, evFork, 0);
    cudaStreamWaitEvent(s_r0, evFork, 0);
    cudaStreamWaitEvent(s_r1, evFork, 0);

    // stage 1: gx0 chunks (serial on s_gx)
    for (int k = 0; k < CHK; k++) {
        gx0_kernel<<<BB, 256, 0, s_gx>>>(x, wih0, bih0, k);
        cudaEventRecord(evG[k], s_gx);
    }
    // stage 2: rec0 chunks (serial on s_r0; each waits its gx0 chunk)
    for (int k = 0; k < CHK; k++) {
        cudaStreamWaitEvent(s_r0, evG[k], 0);
        rec0_kernel<<<128, 256, 0, s_r0>>>(whh0, bhh0, out, k);
        cudaEventRecord(evR0[k], s_r0);
    }
    // stage 3: gxl1 + rec1 chunks (serial on s_r1; gxl1_k waits rec0_k)
    for (int k = 0; k < CHK; k++) {
        cudaStreamWaitEvent(s_r1, evR0[k], 0);
        gxl1_kernel<<<BB, 256, 0, s_r1>>>(wih1, bih1, k);
        rec1_kernel<<<128, 256, 0, s_r1>>>(whh1, bhh1, wcls, bcls, out, k);
    }
    // join everything back to the default stream (transitively covers s_gx, s_r0)
    cudaEventRecord(evJoin, s_r1);
    cudaStreamWaitEvent(0, evJoin, 0);
}